// round 4
// baseline (speedup 1.0000x reference)
#include <cuda_runtime.h>
#include <math.h>
#include <stdint.h>

// B=8, N=64, D=64, E=32. Block = one (b, i_node). Fused:
//   agg[b,i,:] = sum_{jn,j} mask*relu(edges@W_e + b_e)*nodes, then 2-step GRU.
// Inner GEMM: packed fma.rn.f32x2 (2 fp32 FMA / fma-pipe slot).
// A (edges) in smem pre-duplicated as (v,v); W staged to smem via cp.async
// double buffer (fixes R2's L1tex-wavefront bottleneck from direct LDG).

typedef unsigned long long u64;

__device__ __forceinline__ u64 ffma2(u64 a, u64 b, u64 c) {
    u64 d;
    asm("fma.rn.f32x2 %0, %1, %2, %3;" : "=l"(d) : "l"(a), "l"(b), "l"(c));
    return d;
}
__device__ __forceinline__ void unpack2(u64 v, float& lo, float& hi) {
    asm("mov.b64 {%0, %1}, %2;" : "=f"(lo), "=f"(hi) : "l"(v));
}
__device__ __forceinline__ void cp16(uint32_t dst_smem, const void* src) {
    asm volatile("cp.async.ca.shared.global [%0], [%1], 16;" :: "r"(dst_smem), "l"(src));
}

__global__ __launch_bounds__(256, 2) void mp_fused_kernel(
    const float* __restrict__ nodes,   // (8,64,64)
    const float* __restrict__ edges,   // (8,4096,32)
    const float* __restrict__ mask,    // (8,4096,1)
    const float* __restrict__ W_e,     // (32,4096)
    const float* __restrict__ b_e,     // (4096,)
    const float* __restrict__ Kmat,    // (64,192)
    const float* __restrict__ Rmat,    // (64,192)
    const float* __restrict__ gbias,   // (2,192)
    float* __restrict__ out)           // (8,64,64)
{
    // static shared (~35 KB)
    __shared__ float2 edges_dup[32][64];  // [k][edge], duplicated (16KB)
    __shared__ float  wt_sh[64][64];      // mask[e]*nodes[b][j_node][j] (16KB)
    __shared__ float  xrow[64];
    __shared__ float  aggs[64];
    __shared__ float  xk1[192], h1[64], xk2[192], hk2[192];
    // dynamic shared: two 32KB W buffers (32 k x 256 cols each)
    extern __shared__ float Wdyn[];       // [2][32*256]

    const int blk   = blockIdx.x;
    const int b     = blk >> 6;
    const int inode = blk & 63;
    const int t     = threadIdx.x;
    const int lane  = t & 31;
    const int warp  = t >> 5;

    const uint32_t wsh_base = (uint32_t)__cvta_generic_to_shared(Wdyn);

    // ---- stage W chunk 0 via cp.async ----
    {
        #pragma unroll
        for (int u = 0; u < 8; u++) {
            int g = t + u * 256;          // 16B granule 0..2047
            int k = g >> 6, c4 = g & 63;
            cp16(wsh_base + (uint32_t)(k * 256 + c4 * 4) * 4,
                 W_e + (size_t)k * 4096 + c4 * 4);
        }
        asm volatile("cp.async.commit_group;");
    }

    // ---- edges (64 x 32) -> transposed + duplicated shared ----
    {
        const float* ebase = edges + ((size_t)b * 4096 + (size_t)inode * 64) * 32;
        for (int i = t; i < 64 * 8; i += 256) {   // float4 granules
            int e = i >> 3;
            int q = i & 7;
            float4 v = *(const float4*)(ebase + e * 32 + q * 4);
            edges_dup[q * 4 + 0][e] = make_float2(v.x, v.x);
            edges_dup[q * 4 + 1][e] = make_float2(v.y, v.y);
            edges_dup[q * 4 + 2][e] = make_float2(v.z, v.z);
            edges_dup[q * 4 + 3][e] = make_float2(v.w, v.w);
        }
    }
    // ---- wt_sh = mask * nodes, xrow, zero aggs ----
    {
        const float* nb = nodes + (size_t)b * 64 * 64;
        const float* mb = mask  + (size_t)b * 4096 + (size_t)inode * 64;
        for (int i = t; i < 64 * 16; i += 256) {  // float4 granules
            int r = i >> 4, q = i & 15;
            float m = mb[r];
            float4 v = *(const float4*)(nb + r * 64 + q * 4);
            float4 w; w.x = v.x * m; w.y = v.y * m; w.z = v.z * m; w.w = v.w * m;
            *(float4*)&wt_sh[r][q * 4] = w;
        }
        if (t < 16) {
            float4 v = *(const float4*)(nb + inode * 64 + t * 4);
            *(float4*)&xrow[t * 4] = v;
        }
        if (t < 64) aggs[t] = 0.0f;
    }
    __syncthreads();   // edges_dup / wt_sh ready

    const int r0 = warp * 8;          // 8 edge-rows per thread (uniform in warp)
    const int c0 = lane * 8;          // 8 cols per thread, 256 cols per chunk

    for (int it = 0; it < 16; it++) {
        // stage next chunk into the other buffer
        if (it + 1 < 16) {
            uint32_t base = wsh_base + ((it + 1) & 1) * 32768u;
            const float* src = W_e + (size_t)(it + 1) * 256;
            #pragma unroll
            for (int u = 0; u < 8; u++) {
                int g = t + u * 256;
                int k = g >> 6, c4 = g & 63;
                cp16(base + (uint32_t)(k * 256 + c4 * 4) * 4,
                     src + (size_t)k * 4096 + c4 * 4);
            }
            asm volatile("cp.async.commit_group;");
            asm volatile("cp.async.wait_group 1;");
        } else {
            asm volatile("cp.async.wait_group 0;");
        }
        __syncthreads();   // chunk `it` visible to all

        const float* wp = Wdyn + (it & 1) * 8192 + c0;

        u64 acc[8][4];
        #pragma unroll
        for (int i = 0; i < 8; i++)
            #pragma unroll
            for (int j = 0; j < 4; j++) acc[i][j] = 0ull;

        #pragma unroll
        for (int k = 0; k < 32; k++) {
            ulonglong2 A01 = *(const ulonglong2*)&edges_dup[k][r0];
            ulonglong2 A23 = *(const ulonglong2*)&edges_dup[k][r0 + 2];
            ulonglong2 A45 = *(const ulonglong2*)&edges_dup[k][r0 + 4];
            ulonglong2 A67 = *(const ulonglong2*)&edges_dup[k][r0 + 6];
            ulonglong2 B0  = *(const ulonglong2*)(wp + k * 256);
            ulonglong2 B1  = *(const ulonglong2*)(wp + k * 256 + 4);
            u64 ad[8] = {A01.x, A01.y, A23.x, A23.y, A45.x, A45.y, A67.x, A67.y};
            u64 bp[4] = {B0.x, B0.y, B1.x, B1.y};
            #pragma unroll
            for (int i = 0; i < 8; i++)
                #pragma unroll
                for (int j = 0; j < 4; j++)
                    acc[i][j] = ffma2(ad[i], bp[j], acc[i][j]);
        }

        // epilogue: relu(pre + b_e) * (mask*nodes), reduce 8x8 -> scalar
        int cglob = it * 256 + c0;
        int jcol  = c0 & 63;          // j within i-group
        int ig    = cglob >> 6;       // output channel i (0..63)
        float4 bb0 = *(const float4*)(b_e + cglob);
        float4 bb1 = *(const float4*)(b_e + cglob + 4);
        float bb[8] = {bb0.x, bb0.y, bb0.z, bb0.w, bb1.x, bb1.y, bb1.z, bb1.w};
        float s = 0.0f;
        #pragma unroll
        for (int i = 0; i < 8; i++) {
            float4 w0 = *(const float4*)&wt_sh[r0 + i][jcol];
            float4 w1 = *(const float4*)&wt_sh[r0 + i][jcol + 4];
            float wv[8] = {w0.x, w0.y, w0.z, w0.w, w1.x, w1.y, w1.z, w1.w};
            #pragma unroll
            for (int j = 0; j < 4; j++) {
                float lo, hi;
                unpack2(acc[i][j], lo, hi);
                s = fmaf(fmaxf(lo + bb[2 * j],     0.0f), wv[2 * j],     s);
                s = fmaf(fmaxf(hi + bb[2 * j + 1], 0.0f), wv[2 * j + 1], s);
            }
        }
        s += __shfl_down_sync(0xffffffffu, s, 4, 8);
        s += __shfl_down_sync(0xffffffffu, s, 2, 8);
        s += __shfl_down_sync(0xffffffffu, s, 1, 8);
        if ((lane & 7) == 0) atomicAdd(&aggs[ig], s);

        __syncthreads();   // all reads of buf[it&1] done before it's restaged
    }

    // ---- GRU tail ----
    if (t < 192) {
        float s = gbias[t];
        #pragma unroll 8
        for (int k = 0; k < 64; k++) s = fmaf(xrow[k], Kmat[k * 192 + t], s);
        xk1[t] = s;
    }
    __syncthreads();
    if (t < 64) {
        float bz = gbias[192 + t];
        float br = gbias[192 + 64 + t];
        float bh = gbias[192 + 128 + t];
        float z  = 1.0f / (1.0f + expf(-(xk1[t] + bz)));
        float r  = 1.0f / (1.0f + expf(-(xk1[64 + t] + br)));
        float hh = tanhf(xk1[128 + t] + r * bh);
        h1[t] = (1.0f - z) * hh;          // h was 0
    }
    __syncthreads();
    if (t < 192) {
        float s1 = gbias[t];
        float s2 = gbias[192 + t];
        #pragma unroll 8
        for (int k = 0; k < 64; k++) {
            s1 = fmaf(aggs[k], Kmat[k * 192 + t], s1);
            s2 = fmaf(h1[k],   Rmat[k * 192 + t], s2);
        }
        xk2[t] = s1; hk2[t] = s2;
    }
    __syncthreads();
    if (t < 64) {
        float z  = 1.0f / (1.0f + expf(-(xk2[t] + hk2[t])));
        float r  = 1.0f / (1.0f + expf(-(xk2[64 + t] + hk2[64 + t])));
        float hh = tanhf(xk2[128 + t] + r * hk2[128 + t]);
        out[((size_t)b * 64 + inode) * 64 + t] = z * h1[t] + (1.0f - z) * hh;
    }
}

extern "C" void kernel_launch(void* const* d_in, const int* in_sizes, int n_in,
                              void* d_out, int out_size) {
    const float* nodes = (const float*)d_in[0];
    const float* edges = (const float*)d_in[1];
    const float* mask  = (const float*)d_in[2];
    const float* W_e   = (const float*)d_in[3];
    const float* b_e   = (const float*)d_in[4];
    const float* gk    = (const float*)d_in[5];
    const float* gr    = (const float*)d_in[6];
    const float* gb    = (const float*)d_in[7];
    float* out = (float*)d_out;

    cudaFuncSetAttribute(mp_fused_kernel,
                         cudaFuncAttributeMaxDynamicSharedMemorySize, 65536);
    mp_fused_kernel<<<512, 256, 65536>>>(nodes, edges, mask, W_e, b_e,
                                         gk, gr, gb, out);
}

// round 7
// speedup vs baseline: 2.6087x; 2.6087x over previous
#include <cuda_runtime.h>
#include <cuda_bf16.h>
#include <math.h>
#include <stdint.h>

// B=8, N=64, D=64, E=32. GEMM view: (32768 x 32) @ (32 x 4096), fused
// relu/mask/reduce epilogue + GRU tail. mma.sync m16n8k16 bf16 (HMMA
// fallback, compute_103-portable), 3-term hi/lo split for fp32-level accuracy.
// W fragments precomputed once into __device__ global in fragment order.

typedef unsigned int u32;

// W fragment buffer: [ig(64)][nt(8)][term(2)][n(8)][q(4)][kt*2+h(4)] u32
__device__ uint4 g_Wfrag4[32768];   // 131072 u32 = 512 KB

static __device__ __forceinline__ void split2(float v0, float v1, u32& hi, u32& lo) {
    __nv_bfloat16 h0 = __float2bfloat16(v0);
    __nv_bfloat16 h1 = __float2bfloat16(v1);
    __nv_bfloat16 l0 = __float2bfloat16(v0 - __bfloat162float(h0));
    __nv_bfloat16 l1 = __float2bfloat16(v1 - __bfloat162float(h1));
    hi = ((u32)__bfloat16_as_ushort(h1) << 16) | (u32)__bfloat16_as_ushort(h0);
    lo = ((u32)__bfloat16_as_ushort(l1) << 16) | (u32)__bfloat16_as_ushort(l0);
}

#define MMA16816(c0,c1,c2,c3,a0,a1,a2,a3,b0,b1) \
    asm volatile("mma.sync.aligned.m16n8k16.row.col.f32.bf16.bf16.f32 " \
        "{%0,%1,%2,%3},{%4,%5,%6,%7},{%8,%9},{%0,%1,%2,%3};" \
        : "+f"(c0),"+f"(c1),"+f"(c2),"+f"(c3) \
        : "r"(a0),"r"(a1),"r"(a2),"r"(a3),"r"(b0),"r"(b1))

// ---------------- converter: W_e -> bf16 hi/lo fragments ----------------
__global__ void conv_w_kernel(const float* __restrict__ W_e) {
    // blockIdx.x = global k-pair qg (0..15); k = 2*qg, 2*qg+1
    int qg = blockIdx.x;
    int kt = qg >> 3, h = (qg >> 2) & 1, q = qg & 3;
    int k0 = qg * 2;
    u32* W = (u32*)g_Wfrag4;
    for (int col = threadIdx.x; col < 4096; col += 256) {
        float w0 = W_e[(size_t)k0 * 4096 + col];
        float w1 = W_e[(size_t)(k0 + 1) * 4096 + col];
        u32 hi, lo; split2(w0, w1, hi, lo);
        int ig = col >> 6, nt = (col >> 3) & 7, n = col & 7;
        int base = ((((ig * 8 + nt) * 2 + 0) * 8 + n) * 4 + q) * 4 + kt * 2 + h;
        W[base]       = hi;   // term 0 (hi)
        W[base + 128] = lo;   // term 1 (lo); term stride = 8*4*4
    }
}

// ---------------- main kernel ----------------
// smem layout (dynamic)
#define OFF_APK   0        // 2*128*20 u32 = 20480 B, row stride 20 u32 (pad)
#define OFF_WT    20480    // 128 x 68 f = 34816 B
#define OFF_BIAS  55296    // 4096 f = 16384 B
#define OFF_AGGS  71680    // 128 f
#define OFF_XROW  72192    // 128 f
#define OFF_XK1   72704    // 192 f
#define OFF_H1    73472    // 64 f
#define OFF_XK2   73728    // 192 f
#define OFF_HK2   74496    // 192 f
#define SMEM_SZ   75264

__global__ __launch_bounds__(256, 2) void mp_mma_kernel(
    const float* __restrict__ nodes,   // (8,64,64)
    const float* __restrict__ edges,   // (8,4096,32)
    const float* __restrict__ mask,    // (8,4096,1)
    const float* __restrict__ b_e,     // (4096,)
    const float* __restrict__ Kmat,    // (64,192)
    const float* __restrict__ Rmat,    // (64,192)
    const float* __restrict__ gbias,   // (2,192)
    float* __restrict__ out)           // (8,64,64)
{
    extern __shared__ char sm[];
    u32*   Apk     = (u32*)(sm + OFF_APK);
    float* wt      = (float*)(sm + OFF_WT);
    float* bias_sh = (float*)(sm + OFF_BIAS);
    float* aggs    = (float*)(sm + OFF_AGGS);
    float* xrow    = (float*)(sm + OFF_XROW);
    float* xk1     = (float*)(sm + OFF_XK1);
    float* h1      = (float*)(sm + OFF_H1);
    float* xk2     = (float*)(sm + OFF_XK2);
    float* hk2     = (float*)(sm + OFF_HK2);

    const int t    = threadIdx.x;
    const int lane = t & 31;
    const int wid  = t >> 5;
    const int b    = blockIdx.x >> 5;
    const int pair = blockIdx.x & 31;

    // ---- init: aggs, bias, wt, xrow ----
    if (t < 128) aggs[t] = 0.0f;
    for (int i = t; i < 1024; i += 256)
        *(float4*)(bias_sh + i * 4) = *(const float4*)(b_e + i * 4);
    for (int i = t; i < 128 * 16; i += 256) {
        int m = i >> 4, qq = i & 15;
        int jn = m & 63, il = m >> 6;
        float mv = mask[(size_t)b * 4096 + (pair * 2 + il) * 64 + jn];
        float4 x = *(const float4*)(nodes + ((size_t)b * 64 + jn) * 64 + qq * 4);
        float4 w; w.x = x.x * mv; w.y = x.y * mv; w.z = x.z * mv; w.w = x.w * mv;
        *(float4*)(wt + m * 68 + qq * 4) = w;
    }
    if (t < 128)
        xrow[t] = nodes[((size_t)b * 64 + pair * 2 + (t >> 6)) * 64 + (t & 63)];

    // ---- A conversion: edges rows -> hi/lo packed k-pairs in smem ----
    {
        int m = t >> 1, half = t & 1;
        const float* ar = edges + ((size_t)(b * 4096 + pair * 128 + m)) * 32 + half * 16;
        float v[16];
        #pragma unroll
        for (int i = 0; i < 16; i += 4) {
            float4 x = *(const float4*)(ar + i);
            v[i] = x.x; v[i + 1] = x.y; v[i + 2] = x.z; v[i + 3] = x.w;
        }
        #pragma unroll
        for (int i = 0; i < 16; i += 2) {
            int qg = half * 8 + (i >> 1);   // global k-pair 0..15
            u32 hi, lo; split2(v[i], v[i + 1], hi, lo);
            Apk[m * 20 + qg]           = hi;
            Apk[(128 + m) * 20 + qg]   = lo;
        }
    }
    __syncthreads();

    const int q  = lane & 3;     // k-pair / col-pair index
    const int rr = lane >> 2;    // row / n index

    for (int igl = 0; igl < 8; igl++) {
        int ig = wid * 8 + igl;

        // B fragments for this i-group: held in registers across all m-tiles
        uint4 Bf[8][2];
        #pragma unroll
        for (int nt = 0; nt < 8; nt++) {
            Bf[nt][0] = g_Wfrag4[((ig * 8 + nt) * 2 + 0) * 32 + lane];
            Bf[nt][1] = g_Wfrag4[((ig * 8 + nt) * 2 + 1) * 32 + lane];
        }

        for (int mt = 0; mt < 8; mt++) {
            const int mrow = mt * 16 + rr;
            // A fragments (hi, lo) x 2 ktiles
            u32 Ah[2][4], Al[2][4];
            #pragma unroll
            for (int kt = 0; kt < 2; kt++) {
                Ah[kt][0] = Apk[mrow * 20 + kt * 8 + q];
                Ah[kt][1] = Apk[(mrow + 8) * 20 + kt * 8 + q];
                Ah[kt][2] = Apk[mrow * 20 + kt * 8 + q + 4];
                Ah[kt][3] = Apk[(mrow + 8) * 20 + kt * 8 + q + 4];
                Al[kt][0] = Apk[(128 + mrow) * 20 + kt * 8 + q];
                Al[kt][1] = Apk[(128 + mrow + 8) * 20 + kt * 8 + q];
                Al[kt][2] = Apk[(128 + mrow) * 20 + kt * 8 + q + 4];
                Al[kt][3] = Apk[(128 + mrow + 8) * 20 + kt * 8 + q + 4];
            }

            float s = 0.0f;
            #pragma unroll
            for (int nt = 0; nt < 8; nt++) {
                float2 bb = *(const float2*)(bias_sh + ig * 64 + nt * 8 + 2 * q);
                float c0 = bb.x, c1 = bb.y, c2 = bb.x, c3 = bb.y;  // bias folded
                // hi*hi
                MMA16816(c0,c1,c2,c3, Ah[0][0],Ah[0][1],Ah[0][2],Ah[0][3],
                         Bf[nt][0].x, Bf[nt][0].y);
                MMA16816(c0,c1,c2,c3, Ah[1][0],Ah[1][1],Ah[1][2],Ah[1][3],
                         Bf[nt][0].z, Bf[nt][0].w);
                // lo*hi
                MMA16816(c0,c1,c2,c3, Al[0][0],Al[0][1],Al[0][2],Al[0][3],
                         Bf[nt][0].x, Bf[nt][0].y);
                MMA16816(c0,c1,c2,c3, Al[1][0],Al[1][1],Al[1][2],Al[1][3],
                         Bf[nt][0].z, Bf[nt][0].w);
                // hi*lo
                MMA16816(c0,c1,c2,c3, Ah[0][0],Ah[0][1],Ah[0][2],Ah[0][3],
                         Bf[nt][1].x, Bf[nt][1].y);
                MMA16816(c0,c1,c2,c3, Ah[1][0],Ah[1][1],Ah[1][2],Ah[1][3],
                         Bf[nt][1].z, Bf[nt][1].w);
                // epilogue: relu * wt, accumulate
                float2 w0 = *(const float2*)(wt + mrow * 68 + nt * 8 + 2 * q);
                float2 w1 = *(const float2*)(wt + (mrow + 8) * 68 + nt * 8 + 2 * q);
                s = fmaf(fmaxf(c0, 0.0f), w0.x, s);
                s = fmaf(fmaxf(c1, 0.0f), w0.y, s);
                s = fmaf(fmaxf(c2, 0.0f), w1.x, s);
                s = fmaf(fmaxf(c3, 0.0f), w1.y, s);
            }
            // full-warp reduce (all lanes belong to same agg[il][ig])
            #pragma unroll
            for (int off = 16; off; off >>= 1)
                s += __shfl_down_sync(0xffffffffu, s, off);
            if (lane == 0) atomicAdd(&aggs[(mt >> 2) * 64 + ig], s);
        }
    }
    __syncthreads();

    // ---- GRU tail: 2 inodes ----
    for (int il2 = 0; il2 < 2; il2++) {
        __syncthreads();
        if (t < 192) {
            float s = gbias[t];
            #pragma unroll 8
            for (int k = 0; k < 64; k++)
                s = fmaf(xrow[il2 * 64 + k], Kmat[k * 192 + t], s);
            xk1[t] = s;
        }
        __syncthreads();
        if (t < 64) {
            float z  = 1.0f / (1.0f + expf(-(xk1[t] + gbias[192 + t])));
            float r  = 1.0f / (1.0f + expf(-(xk1[64 + t] + gbias[256 + t])));
            float hh = tanhf(xk1[128 + t] + r * gbias[320 + t]);
            h1[t] = (1.0f - z) * hh;   // h was 0
        }
        __syncthreads();
        if (t < 192) {
            float s1 = gbias[t], s2 = gbias[192 + t];
            #pragma unroll 8
            for (int k = 0; k < 64; k++) {
                s1 = fmaf(aggs[il2 * 64 + k], Kmat[k * 192 + t], s1);
                s2 = fmaf(h1[k],              Rmat[k * 192 + t], s2);
            }
            xk2[t] = s1; hk2[t] = s2;
        }
        __syncthreads();
        if (t < 64) {
            float z  = 1.0f / (1.0f + expf(-(xk2[t] + hk2[t])));
            float r  = 1.0f / (1.0f + expf(-(xk2[64 + t] + hk2[64 + t])));
            float hh = tanhf(xk2[128 + t] + r * hk2[128 + t]);
            out[((size_t)(b * 64 + pair * 2 + il2)) * 64 + t] =
                z * h1[t] + (1.0f - z) * hh;
        }
    }
}

extern "C" void kernel_launch(void* const* d_in, const int* in_sizes, int n_in,
                              void* d_out, int out_size) {
    const float* nodes = (const float*)d_in[0];
    const float* edges = (const float*)d_in[1];
    const float* mask  = (const float*)d_in[2];
    const float* W_e   = (const float*)d_in[3];
    const float* b_e   = (const float*)d_in[4];
    const float* gk    = (const float*)d_in[5];
    const float* gr    = (const float*)d_in[6];
    const float* gb    = (const float*)d_in[7];
    float* out = (float*)d_out;

    conv_w_kernel<<<16, 256>>>(W_e);

    static int attr_set = 0;
    cudaFuncSetAttribute(mp_mma_kernel,
                         cudaFuncAttributeMaxDynamicSharedMemorySize, SMEM_SZ);
    (void)attr_set;
    mp_mma_kernel<<<256, 256, SMEM_SZ>>>(nodes, edges, mask, b_e,
                                         gk, gr, gb, out);
}